// round 1
// baseline (speedup 1.0000x reference)
#include <cuda_runtime.h>
#include <cuda_bf16.h>
#include <stdint.h>

// Problem constants (MixtralSparseMoeBlock: B=2,S=2048 -> T=4096, H=1024, F=3584, E=8, top-2)
#define T_TOKENS 4096
#define H_DIM    1024
#define F_DIM    3584
#define NE       8

// ---------------- scratch (device globals; no allocation allowed) ----------------
__device__ int   g_counts[NE];
__device__ int   g_tok[NE * T_TOKENS];
__device__ float g_wt[NE * T_TOKENS];
// inner activations, fixed stride T_TOKENS slots per expert (worst case), fp32
__device__ float g_inner[(size_t)NE * T_TOKENS * F_DIM];

// ---------------- helpers ----------------
__device__ __forceinline__ uint32_t f2tf32(float f) {
    uint32_t u;
    asm("cvt.rn.tf32.f32 %0, %1;" : "=r"(u) : "f"(f));
    return u;
}

__device__ __forceinline__ void mma_tf32(float* d, const uint32_t* a, const uint32_t* b) {
    asm volatile(
        "mma.sync.aligned.m16n8k8.row.col.f32.tf32.tf32.f32 "
        "{%0,%1,%2,%3}, {%4,%5,%6,%7}, {%8,%9}, {%0,%1,%2,%3};"
        : "+f"(d[0]), "+f"(d[1]), "+f"(d[2]), "+f"(d[3])
        : "r"(a[0]), "r"(a[1]), "r"(a[2]), "r"(a[3]), "r"(b[0]), "r"(b[1]));
}

// ---------------- kernel 0: zero y + counts ----------------
__global__ void zero_kernel(float* __restrict__ y) {
    size_t n = (size_t)T_TOKENS * H_DIM;
    for (size_t i = (size_t)blockIdx.x * blockDim.x + threadIdx.x; i < n;
         i += (size_t)gridDim.x * blockDim.x)
        y[i] = 0.0f;
    if (blockIdx.x == 0 && threadIdx.x < NE) g_counts[threadIdx.x] = 0;
}

// ---------------- kernel 1: router (one warp per token) ----------------
__global__ void router_kernel(const float* __restrict__ x,
                              const float* __restrict__ gw,
                              float* __restrict__ out_logits) {
    int warp = blockIdx.x * (blockDim.x >> 5) + (threadIdx.x >> 5);
    int lane = threadIdx.x & 31;
    if (warp >= T_TOKENS) return;

    float acc[NE];
#pragma unroll
    for (int e = 0; e < NE; e++) acc[e] = 0.0f;

    const float* xr = x + (size_t)warp * H_DIM;
    for (int h = lane; h < H_DIM; h += 32) {
        float xv = xr[h];
        const float4* g4 = reinterpret_cast<const float4*>(gw + (size_t)h * NE);
        float4 g0 = g4[0], g1 = g4[1];
        acc[0] += xv * g0.x; acc[1] += xv * g0.y;
        acc[2] += xv * g0.z; acc[3] += xv * g0.w;
        acc[4] += xv * g1.x; acc[5] += xv * g1.y;
        acc[6] += xv * g1.z; acc[7] += xv * g1.w;
    }
#pragma unroll
    for (int e = 0; e < NE; e++) {
#pragma unroll
        for (int off = 16; off >= 1; off >>= 1)
            acc[e] += __shfl_xor_sync(0xFFFFFFFFu, acc[e], off);
    }

    if (lane == 0) {
#pragma unroll
        for (int e = 0; e < NE; e++) out_logits[(size_t)warp * NE + e] = acc[e];

        // top-2 (strict > picks lowest index on ties, matching top_k)
        int i0 = 0;
#pragma unroll
        for (int e = 1; e < NE; e++)
            if (acc[e] > acc[i0]) i0 = e;
        int i1 = (i0 == 0) ? 1 : 0;
#pragma unroll
        for (int e = 0; e < NE; e++)
            if (e != i0 && acc[e] > acc[i1]) i1 = e;

        // renormalized softmax over the two selected: softmax denom cancels
        float e1 = __expf(acc[i1] - acc[i0]);  // <= 1
        float w0 = 1.0f / (1.0f + e1);
        float w1 = e1 / (1.0f + e1);

        int s0 = atomicAdd(&g_counts[i0], 1);
        g_tok[i0 * T_TOKENS + s0] = warp;
        g_wt[i0 * T_TOKENS + s0] = w0;
        int s1 = atomicAdd(&g_counts[i1], 1);
        g_tok[i1 * T_TOKENS + s1] = warp;
        g_wt[i1 * T_TOKENS + s1] = w1;
    }
}

// ---------------- kernel 2: up+gate GEMM with fused SwiGLU, weight folded ----------------
// C[m][f] = silu(x@w_up) * (x@w_gate) * combine_weight  -> g_inner
// Block: 128 threads, tile BM=64 x BN=64, BK=32. 4 warps in 2x2, warp tile 32x32.
__global__ __launch_bounds__(128) void upgate_kernel(const float* __restrict__ x,
                                                     const float* __restrict__ w_up_all,
                                                     const float* __restrict__ w_gate_all) {
    const int e = blockIdx.z;
    const int cnt = g_counts[e];
    const int m0 = blockIdx.y * 64;
    if (m0 >= cnt) return;
    const int f0 = blockIdx.x * 64;

    __shared__ uint32_t sA[64][36];
    __shared__ uint32_t sBu[32][72];
    __shared__ uint32_t sBg[32][72];

    const int tid = threadIdx.x;
    const int lane = tid & 31, wid = tid >> 5;
    const int warp_m = (wid >> 1) * 32, warp_n = (wid & 1) * 32;
    const int gid = lane >> 2, t4 = lane & 3;

    float accU[2][4][4], accG[2][4][4];
#pragma unroll
    for (int mt = 0; mt < 2; mt++)
#pragma unroll
        for (int nt = 0; nt < 4; nt++)
#pragma unroll
            for (int i = 0; i < 4; i++) { accU[mt][nt][i] = 0.f; accG[mt][nt][i] = 0.f; }

    const float* wu = w_up_all + (size_t)e * H_DIM * F_DIM;
    const float* wg = w_gate_all + (size_t)e * H_DIM * F_DIM;

    // prefetch token ids for the 4 A-rows this thread loads (row = (tid+128j)>>3)
    int tokr[4];
#pragma unroll
    for (int j = 0; j < 4; j++) {
        int r = (tid + 128 * j) >> 3;
        int m = m0 + r;
        tokr[j] = (m < cnt) ? g_tok[e * T_TOKENS + m] : -1;
    }

    for (int k0 = 0; k0 < H_DIM; k0 += 32) {
        __syncthreads();
        // load A (x gathered rows), convert to tf32
#pragma unroll
        for (int j = 0; j < 4; j++) {
            int i = tid + 128 * j;
            int r = i >> 3, kq = i & 7;
            float4 v = make_float4(0.f, 0.f, 0.f, 0.f);
            if (tokr[j] >= 0)
                v = *reinterpret_cast<const float4*>(x + (size_t)tokr[j] * H_DIM + k0 + kq * 4);
            uint32_t* p = &sA[r][kq * 4];
            p[0] = f2tf32(v.x); p[1] = f2tf32(v.y); p[2] = f2tf32(v.z); p[3] = f2tf32(v.w);
        }
        // load B_up, B_gate
#pragma unroll
        for (int j = 0; j < 4; j++) {
            int i = tid + 128 * j;
            int r = i >> 4, nq = i & 15;
            size_t off = (size_t)(k0 + r) * F_DIM + f0 + nq * 4;
            float4 vu = *reinterpret_cast<const float4*>(wu + off);
            float4 vg = *reinterpret_cast<const float4*>(wg + off);
            uint32_t* pu = &sBu[r][nq * 4];
            pu[0] = f2tf32(vu.x); pu[1] = f2tf32(vu.y); pu[2] = f2tf32(vu.z); pu[3] = f2tf32(vu.w);
            uint32_t* pg = &sBg[r][nq * 4];
            pg[0] = f2tf32(vg.x); pg[1] = f2tf32(vg.y); pg[2] = f2tf32(vg.z); pg[3] = f2tf32(vg.w);
        }
        __syncthreads();

#pragma unroll
        for (int ks = 0; ks < 4; ks++) {
            uint32_t a[2][4], bu[4][2], bg[4][2];
#pragma unroll
            for (int mt = 0; mt < 2; mt++) {
                int rb = warp_m + mt * 16;
                a[mt][0] = sA[rb + gid][ks * 8 + t4];
                a[mt][1] = sA[rb + gid + 8][ks * 8 + t4];
                a[mt][2] = sA[rb + gid][ks * 8 + t4 + 4];
                a[mt][3] = sA[rb + gid + 8][ks * 8 + t4 + 4];
            }
#pragma unroll
            for (int nt = 0; nt < 4; nt++) {
                int c = warp_n + nt * 8 + gid;
                bu[nt][0] = sBu[ks * 8 + t4][c];
                bu[nt][1] = sBu[ks * 8 + t4 + 4][c];
                bg[nt][0] = sBg[ks * 8 + t4][c];
                bg[nt][1] = sBg[ks * 8 + t4 + 4][c];
            }
#pragma unroll
            for (int mt = 0; mt < 2; mt++)
#pragma unroll
                for (int nt = 0; nt < 4; nt++) {
                    mma_tf32(accU[mt][nt], a[mt], bu[nt]);
                    mma_tf32(accG[mt][nt], a[mt], bg[nt]);
                }
        }
    }

    // epilogue: silu(up) * gate * combine_weight -> g_inner
#pragma unroll
    for (int mt = 0; mt < 2; mt++) {
#pragma unroll
        for (int half = 0; half < 2; half++) {
            int m = m0 + warp_m + mt * 16 + gid + half * 8;
            if (m >= cnt) continue;
            float wgt = g_wt[e * T_TOKENS + m];
            float* dst = g_inner + ((size_t)e * T_TOKENS + m) * F_DIM;
#pragma unroll
            for (int nt = 0; nt < 4; nt++) {
#pragma unroll
                for (int c = 0; c < 2; c++) {
                    int i = half * 2 + c;
                    int f = f0 + warp_n + nt * 8 + 2 * t4 + c;
                    float u = accU[mt][nt][i];
                    float g = accG[mt][nt][i];
                    float s = u / (1.0f + __expf(-u));
                    dst[f] = s * g * wgt;
                }
            }
        }
    }
}

// ---------------- kernel 3: down-projection GEMM + scatter-add ----------------
// y[tok] += inner[m] @ w_down[e]   (combine weight already folded into inner)
__global__ __launch_bounds__(128) void down_kernel(const float* __restrict__ w_down_all,
                                                   float* __restrict__ y) {
    const int e = blockIdx.z;
    const int cnt = g_counts[e];
    const int m0 = blockIdx.y * 64;
    if (m0 >= cnt) return;
    const int h0 = blockIdx.x * 64;

    __shared__ uint32_t sA[64][36];
    __shared__ uint32_t sB[32][72];

    const int tid = threadIdx.x;
    const int lane = tid & 31, wid = tid >> 5;
    const int warp_m = (wid >> 1) * 32, warp_n = (wid & 1) * 32;
    const int gid = lane >> 2, t4 = lane & 3;

    float acc[2][4][4];
#pragma unroll
    for (int mt = 0; mt < 2; mt++)
#pragma unroll
        for (int nt = 0; nt < 4; nt++)
#pragma unroll
            for (int i = 0; i < 4; i++) acc[mt][nt][i] = 0.f;

    const float* wd = w_down_all + (size_t)e * F_DIM * H_DIM;
    const float* Abase = g_inner + (size_t)e * T_TOKENS * F_DIM;

    for (int k0 = 0; k0 < F_DIM; k0 += 32) {
        __syncthreads();
#pragma unroll
        for (int j = 0; j < 4; j++) {
            int i = tid + 128 * j;
            int r = i >> 3, kq = i & 7;
            int m = m0 + r;
            float4 v = make_float4(0.f, 0.f, 0.f, 0.f);
            if (m < cnt)
                v = *reinterpret_cast<const float4*>(Abase + (size_t)m * F_DIM + k0 + kq * 4);
            uint32_t* p = &sA[r][kq * 4];
            p[0] = f2tf32(v.x); p[1] = f2tf32(v.y); p[2] = f2tf32(v.z); p[3] = f2tf32(v.w);
        }
#pragma unroll
        for (int j = 0; j < 4; j++) {
            int i = tid + 128 * j;
            int r = i >> 4, nq = i & 15;
            float4 v = *reinterpret_cast<const float4*>(wd + (size_t)(k0 + r) * H_DIM + h0 + nq * 4);
            uint32_t* p = &sB[r][nq * 4];
            p[0] = f2tf32(v.x); p[1] = f2tf32(v.y); p[2] = f2tf32(v.z); p[3] = f2tf32(v.w);
        }
        __syncthreads();

#pragma unroll
        for (int ks = 0; ks < 4; ks++) {
            uint32_t a[2][4], b[4][2];
#pragma unroll
            for (int mt = 0; mt < 2; mt++) {
                int rb = warp_m + mt * 16;
                a[mt][0] = sA[rb + gid][ks * 8 + t4];
                a[mt][1] = sA[rb + gid + 8][ks * 8 + t4];
                a[mt][2] = sA[rb + gid][ks * 8 + t4 + 4];
                a[mt][3] = sA[rb + gid + 8][ks * 8 + t4 + 4];
            }
#pragma unroll
            for (int nt = 0; nt < 4; nt++) {
                int c = warp_n + nt * 8 + gid;
                b[nt][0] = sB[ks * 8 + t4][c];
                b[nt][1] = sB[ks * 8 + t4 + 4][c];
            }
#pragma unroll
            for (int mt = 0; mt < 2; mt++)
#pragma unroll
                for (int nt = 0; nt < 4; nt++)
                    mma_tf32(acc[mt][nt], a[mt], b[nt]);
        }
    }

    // epilogue: scatter-add to y rows (exactly 2 contributions per token, commutative)
#pragma unroll
    for (int mt = 0; mt < 2; mt++) {
#pragma unroll
        for (int half = 0; half < 2; half++) {
            int m = m0 + warp_m + mt * 16 + gid + half * 8;
            if (m >= cnt) continue;
            int tok = g_tok[e * T_TOKENS + m];
            float* dst = y + (size_t)tok * H_DIM;
#pragma unroll
            for (int nt = 0; nt < 4; nt++) {
#pragma unroll
                for (int c = 0; c < 2; c++) {
                    int i = half * 2 + c;
                    int h = h0 + warp_n + nt * 8 + 2 * t4 + c;
                    atomicAdd(&dst[h], acc[mt][nt][i]);
                }
            }
        }
    }
}

// ---------------- launch ----------------
extern "C" void kernel_launch(void* const* d_in, const int* in_sizes, int n_in,
                              void* d_out, int out_size) {
    const float* x      = (const float*)d_in[0];  // [2,2048,1024]
    const float* gw     = (const float*)d_in[1];  // [1024,8]
    const float* w_up   = (const float*)d_in[2];  // [8,1024,3584]
    const float* w_gate = (const float*)d_in[3];  // [8,1024,3584]
    const float* w_down = (const float*)d_in[4];  // [8,3584,1024]

    float* out = (float*)d_out;
    float* y = out;                                    // [T, H]
    float* logits = out + (size_t)T_TOKENS * H_DIM;    // [T, E]

    zero_kernel<<<512, 256>>>(y);
    router_kernel<<<T_TOKENS / 8, 256>>>(x, gw, logits);

    dim3 g2(F_DIM / 64, T_TOKENS / 64, NE);
    upgate_kernel<<<g2, 128>>>(x, w_up, w_gate);

    dim3 g3(H_DIM / 64, T_TOKENS / 64, NE);
    down_kernel<<<g3, 128>>>(w_down, y);
}

// round 5
// speedup vs baseline: 1.1803x; 1.1803x over previous
#include <cuda_runtime.h>
#include <cuda_bf16.h>
#include <stdint.h>

// MixtralSparseMoeBlock: B=2,S=2048 -> T=4096, H=1024, F=3584, E=8, top-2
#define T_TOKENS 4096
#define H_DIM    1024
#define F_DIM    3584
#define NE       8

#define BM 128
#define BN 128
#define BKD 32   // down K-chunk
#define BKU 16   // upgate K-chunk

// ---------------- scratch (device globals; no allocation allowed) ----------------
__device__ int   g_counts[NE];
__device__ int   g_tok[NE * T_TOKENS];
__device__ float g_wt[NE * T_TOKENS];
// inner activations (already tf32-converted bits), stride T_TOKENS rows per expert
__device__ float g_inner[(size_t)NE * T_TOKENS * F_DIM];

// ---------------- helpers ----------------
__device__ __forceinline__ uint32_t f2tf32(float f) {
    uint32_t u;
    asm("cvt.rn.tf32.f32 %0, %1;" : "=r"(u) : "f"(f));
    return u;
}

__device__ __forceinline__ void mma_tf32(float* d, const uint32_t* a, const uint32_t* b) {
    asm volatile(
        "mma.sync.aligned.m16n8k8.row.col.f32.tf32.tf32.f32 "
        "{%0,%1,%2,%3}, {%4,%5,%6,%7}, {%8,%9}, {%0,%1,%2,%3};"
        : "+f"(d[0]), "+f"(d[1]), "+f"(d[2]), "+f"(d[3])
        : "r"(a[0]), "r"(a[1]), "r"(a[2]), "r"(a[3]), "r"(b[0]), "r"(b[1]));
}

// ---------------- kernel 0: zero y + counts ----------------
__global__ void zero_kernel(float* __restrict__ y) {
    size_t n = (size_t)T_TOKENS * H_DIM;
    for (size_t i = (size_t)blockIdx.x * blockDim.x + threadIdx.x; i < n;
         i += (size_t)gridDim.x * blockDim.x)
        y[i] = 0.0f;
    if (blockIdx.x == 0 && threadIdx.x < NE) g_counts[threadIdx.x] = 0;
}

// ---------------- kernel 1: router (one warp per token) ----------------
__global__ void router_kernel(const float* __restrict__ x,
                              const float* __restrict__ gw,
                              float* __restrict__ out_logits) {
    int warp = blockIdx.x * (blockDim.x >> 5) + (threadIdx.x >> 5);
    int lane = threadIdx.x & 31;
    if (warp >= T_TOKENS) return;

    float acc[NE];
#pragma unroll
    for (int e = 0; e < NE; e++) acc[e] = 0.0f;

    const float* xr = x + (size_t)warp * H_DIM;
    for (int h = lane; h < H_DIM; h += 32) {
        float xv = xr[h];
        const float4* g4 = reinterpret_cast<const float4*>(gw + (size_t)h * NE);
        float4 g0 = g4[0], g1 = g4[1];
        acc[0] += xv * g0.x; acc[1] += xv * g0.y;
        acc[2] += xv * g0.z; acc[3] += xv * g0.w;
        acc[4] += xv * g1.x; acc[5] += xv * g1.y;
        acc[6] += xv * g1.z; acc[7] += xv * g1.w;
    }
#pragma unroll
    for (int e = 0; e < NE; e++) {
#pragma unroll
        for (int off = 16; off >= 1; off >>= 1)
            acc[e] += __shfl_xor_sync(0xFFFFFFFFu, acc[e], off);
    }

    if (lane == 0) {
#pragma unroll
        for (int e = 0; e < NE; e++) out_logits[(size_t)warp * NE + e] = acc[e];

        int i0 = 0;
#pragma unroll
        for (int e = 1; e < NE; e++)
            if (acc[e] > acc[i0]) i0 = e;
        int i1 = (i0 == 0) ? 1 : 0;
#pragma unroll
        for (int e = 0; e < NE; e++)
            if (e != i0 && acc[e] > acc[i1]) i1 = e;

        float e1 = __expf(acc[i1] - acc[i0]);
        float w0 = 1.0f / (1.0f + e1);
        float w1 = e1 / (1.0f + e1);

        int s0 = atomicAdd(&g_counts[i0], 1);
        g_tok[i0 * T_TOKENS + s0] = warp;
        g_wt[i0 * T_TOKENS + s0] = w0;
        int s1 = atomicAdd(&g_counts[i1], 1);
        g_tok[i1 * T_TOKENS + s1] = warp;
        g_wt[i1 * T_TOKENS + s1] = w1;
    }
}

// =====================================================================================
// kernel 2: up+gate GEMM, fused SwiGLU, combine weight folded, output pre-cvt tf32
// 256 threads, block tile 128(M) x 128(F), BK=16, double-buffered smem,
// warp grid 2x4, warp tile 64x32, each warp accumulates both U and G (A reuse).
// =====================================================================================
#define UG_SA_STRIDE 20              // 16 + 4 pad
#define UG_SA_STAGE  (128 * UG_SA_STRIDE)
#define UG_SB_STRIDE 132             // 128 + 4 pad
#define UG_SB_STAGE  (16 * UG_SB_STRIDE)
#define UG_SMEM_BYTES ((2 * UG_SA_STAGE + 4 * UG_SB_STAGE) * 4)

__global__ __launch_bounds__(256) void upgate_kernel(const float* __restrict__ x,
                                                     const float* __restrict__ w_up_all,
                                                     const float* __restrict__ w_gate_all) {
    const int e = blockIdx.z;
    const int cnt = g_counts[e];
    const int m0 = blockIdx.y * BM;
    if (m0 >= cnt) return;
    const int f0 = blockIdx.x * BN;

    extern __shared__ uint32_t sh[];
    uint32_t* sA  = sh;                                   // [2][128][20]
    uint32_t* sBu = sh + 2 * UG_SA_STAGE;                 // [2][16][132]
    uint32_t* sBg = sBu + 2 * UG_SB_STAGE;                // [2][16][132]

    const int tid = threadIdx.x;
    const int lane = tid & 31, wid = tid >> 5;
    const int warp_m = (wid >> 2) * 64;   // 0 or 64
    const int warp_n = (wid & 3) * 32;    // 0,32,64,96
    const int gid = lane >> 2, t4 = lane & 3;

    float accU[4][4][4], accG[4][4][4];
#pragma unroll
    for (int mt = 0; mt < 4; mt++)
#pragma unroll
        for (int nt = 0; nt < 4; nt++)
#pragma unroll
            for (int i = 0; i < 4; i++) { accU[mt][nt][i] = 0.f; accG[mt][nt][i] = 0.f; }

    const float* wu = w_up_all + (size_t)e * H_DIM * F_DIM;
    const float* wg = w_gate_all + (size_t)e * H_DIM * F_DIM;

    // A loader mapping: 2 float4 per thread per chunk. row = (tid>>2) + 64p, kq = tid&3
    const int arow = tid >> 2, akq = tid & 3;
    const float* aptr[2];
#pragma unroll
    for (int p = 0; p < 2; p++) {
        int m = m0 + arow + 64 * p;
        int tok = (m < cnt) ? g_tok[e * T_TOKENS + m] : -1;
        aptr[p] = (tok >= 0) ? (x + (size_t)tok * H_DIM + akq * 4) : nullptr;
    }
    // B loader mapping: 2 float4 per thread per matrix per chunk. row=(tid>>5)+8p, nq=tid&31
    const int brow = tid >> 5, bnq = tid & 31;

    const int NT = H_DIM / BKU;  // 64

    float4 va[2], vbu[2], vbg[2];
    // ---- prologue: load chunk 0 ----
#pragma unroll
    for (int p = 0; p < 2; p++)
        va[p] = aptr[p] ? *reinterpret_cast<const float4*>(aptr[p]) : make_float4(0,0,0,0);
#pragma unroll
    for (int p = 0; p < 2; p++) {
        size_t off = (size_t)(brow + 8 * p) * F_DIM + f0 + bnq * 4;
        vbu[p] = *reinterpret_cast<const float4*>(wu + off);
        vbg[p] = *reinterpret_cast<const float4*>(wg + off);
    }
#pragma unroll
    for (int p = 0; p < 2; p++) {
        uint4 u = make_uint4(f2tf32(va[p].x), f2tf32(va[p].y), f2tf32(va[p].z), f2tf32(va[p].w));
        *reinterpret_cast<uint4*>(&sA[(arow + 64 * p) * UG_SA_STRIDE + akq * 4]) = u;
        uint4 uu = make_uint4(f2tf32(vbu[p].x), f2tf32(vbu[p].y), f2tf32(vbu[p].z), f2tf32(vbu[p].w));
        *reinterpret_cast<uint4*>(&sBu[(brow + 8 * p) * UG_SB_STRIDE + bnq * 4]) = uu;
        uint4 ug = make_uint4(f2tf32(vbg[p].x), f2tf32(vbg[p].y), f2tf32(vbg[p].z), f2tf32(vbg[p].w));
        *reinterpret_cast<uint4*>(&sBg[(brow + 8 * p) * UG_SB_STRIDE + bnq * 4]) = ug;
    }
    __syncthreads();

    for (int t = 0; t < NT; t++) {
        const int cur = t & 1, nxt = 1 - cur;
        const int k0n = (t + 1) * BKU;
        if (t + 1 < NT) {
#pragma unroll
            for (int p = 0; p < 2; p++)
                va[p] = aptr[p] ? *reinterpret_cast<const float4*>(aptr[p] + k0n)
                                : make_float4(0,0,0,0);
#pragma unroll
            for (int p = 0; p < 2; p++) {
                size_t off = (size_t)(k0n + brow + 8 * p) * F_DIM + f0 + bnq * 4;
                vbu[p] = *reinterpret_cast<const float4*>(wu + off);
                vbg[p] = *reinterpret_cast<const float4*>(wg + off);
            }
        }

        const uint32_t* cA  = sA  + cur * UG_SA_STAGE;
        const uint32_t* cBu = sBu + cur * UG_SB_STAGE;
        const uint32_t* cBg = sBg + cur * UG_SB_STAGE;
#pragma unroll
        for (int ks = 0; ks < 2; ks++) {
            uint32_t a[4][4], bu[4][2], bg[4][2];
#pragma unroll
            for (int mt = 0; mt < 4; mt++) {
                int rb = warp_m + mt * 16;
                a[mt][0] = cA[(rb + gid) * UG_SA_STRIDE + ks * 8 + t4];
                a[mt][1] = cA[(rb + gid + 8) * UG_SA_STRIDE + ks * 8 + t4];
                a[mt][2] = cA[(rb + gid) * UG_SA_STRIDE + ks * 8 + t4 + 4];
                a[mt][3] = cA[(rb + gid + 8) * UG_SA_STRIDE + ks * 8 + t4 + 4];
            }
#pragma unroll
            for (int nt = 0; nt < 4; nt++) {
                int c = warp_n + nt * 8 + gid;
                bu[nt][0] = cBu[(ks * 8 + t4) * UG_SB_STRIDE + c];
                bu[nt][1] = cBu[(ks * 8 + t4 + 4) * UG_SB_STRIDE + c];
                bg[nt][0] = cBg[(ks * 8 + t4) * UG_SB_STRIDE + c];
                bg[nt][1] = cBg[(ks * 8 + t4 + 4) * UG_SB_STRIDE + c];
            }
#pragma unroll
            for (int mt = 0; mt < 4; mt++)
#pragma unroll
                for (int nt = 0; nt < 4; nt++) {
                    mma_tf32(accU[mt][nt], a[mt], bu[nt]);
                    mma_tf32(accG[mt][nt], a[mt], bg[nt]);
                }
        }

        if (t + 1 < NT) {
#pragma unroll
            for (int p = 0; p < 2; p++) {
                uint4 u = make_uint4(f2tf32(va[p].x), f2tf32(va[p].y), f2tf32(va[p].z), f2tf32(va[p].w));
                *reinterpret_cast<uint4*>(&sA[nxt * UG_SA_STAGE + (arow + 64 * p) * UG_SA_STRIDE + akq * 4]) = u;
                uint4 uu = make_uint4(f2tf32(vbu[p].x), f2tf32(vbu[p].y), f2tf32(vbu[p].z), f2tf32(vbu[p].w));
                *reinterpret_cast<uint4*>(&sBu[nxt * UG_SB_STAGE + (brow + 8 * p) * UG_SB_STRIDE + bnq * 4]) = uu;
                uint4 ug = make_uint4(f2tf32(vbg[p].x), f2tf32(vbg[p].y), f2tf32(vbg[p].z), f2tf32(vbg[p].w));
                *reinterpret_cast<uint4*>(&sBg[nxt * UG_SB_STAGE + (brow + 8 * p) * UG_SB_STRIDE + bnq * 4]) = ug;
            }
        }
        __syncthreads();
    }

    // epilogue: silu(U)*G*w -> g_inner, stored as tf32 bits for the down GEMM
#pragma unroll
    for (int mt = 0; mt < 4; mt++) {
#pragma unroll
        for (int half = 0; half < 2; half++) {
            int m = m0 + warp_m + mt * 16 + gid + half * 8;
            if (m >= cnt) continue;
            float wgt = g_wt[e * T_TOKENS + m];
            float* dst = g_inner + ((size_t)e * T_TOKENS + m) * F_DIM;
#pragma unroll
            for (int nt = 0; nt < 4; nt++) {
#pragma unroll
                for (int c = 0; c < 2; c++) {
                    int i = half * 2 + c;
                    int f = f0 + warp_n + nt * 8 + 2 * t4 + c;
                    float u = accU[mt][nt][i];
                    float g = accG[mt][nt][i];
                    float s = u / (1.0f + __expf(-u));
                    dst[f] = __uint_as_float(f2tf32(s * g * wgt));
                }
            }
        }
    }
}

// =====================================================================================
// kernel 3: down GEMM + scatter-add. 256 threads, 128x128 tile, BK=32, double-buffered.
// A (g_inner) already tf32 bits -> raw copy to smem; B cvt at STS.
// =====================================================================================
#define DN_SA_STRIDE 36              // 32 + 4 pad
#define DN_SA_STAGE  (128 * DN_SA_STRIDE)
#define DN_SB_STRIDE 132
#define DN_SB_STAGE  (32 * DN_SB_STRIDE)
#define DN_SMEM_BYTES ((2 * DN_SA_STAGE + 2 * DN_SB_STAGE) * 4)

__global__ __launch_bounds__(256) void down_kernel(const float* __restrict__ w_down_all,
                                                   float* __restrict__ y) {
    const int e = blockIdx.z;
    const int cnt = g_counts[e];
    const int m0 = blockIdx.y * BM;
    if (m0 >= cnt) return;
    const int h0 = blockIdx.x * BN;

    extern __shared__ uint32_t sh[];
    uint32_t* sA = sh;                       // [2][128][36]
    uint32_t* sB = sh + 2 * DN_SA_STAGE;     // [2][32][132]

    const int tid = threadIdx.x;
    const int lane = tid & 31, wid = tid >> 5;
    const int warp_m = (wid >> 2) * 64;
    const int warp_n = (wid & 3) * 32;
    const int gid = lane >> 2, t4 = lane & 3;

    float acc[4][4][4];
#pragma unroll
    for (int mt = 0; mt < 4; mt++)
#pragma unroll
        for (int nt = 0; nt < 4; nt++)
#pragma unroll
            for (int i = 0; i < 4; i++) acc[mt][nt][i] = 0.f;

    const float* wd = w_down_all + (size_t)e * F_DIM * H_DIM;
    const float* Abase = g_inner + (size_t)e * T_TOKENS * F_DIM;

    // A: 4 float4/thread/chunk. row=(tid>>3)+32p, kq=tid&7
    const int arow = tid >> 3, akq = tid & 7;
    const float* aptr[4];
#pragma unroll
    for (int p = 0; p < 4; p++) {
        int m = m0 + arow + 32 * p;
        aptr[p] = (m < cnt) ? (Abase + (size_t)m * F_DIM + akq * 4) : nullptr;
    }
    // B: 4 float4/thread/chunk. row=(tid>>5)+8p, nq=tid&31
    const int brow = tid >> 5, bnq = tid & 31;

    const int NT = F_DIM / BKD;  // 112

    float4 va[4], vb[4];
#pragma unroll
    for (int p = 0; p < 4; p++)
        va[p] = aptr[p] ? *reinterpret_cast<const float4*>(aptr[p]) : make_float4(0,0,0,0);
#pragma unroll
    for (int p = 0; p < 4; p++)
        vb[p] = *reinterpret_cast<const float4*>(wd + (size_t)(brow + 8 * p) * H_DIM + h0 + bnq * 4);
#pragma unroll
    for (int p = 0; p < 4; p++) {
        *reinterpret_cast<float4*>(&sA[(arow + 32 * p) * DN_SA_STRIDE + akq * 4]) = va[p];
        uint4 ub = make_uint4(f2tf32(vb[p].x), f2tf32(vb[p].y), f2tf32(vb[p].z), f2tf32(vb[p].w));
        *reinterpret_cast<uint4*>(&sB[(brow + 8 * p) * DN_SB_STRIDE + bnq * 4]) = ub;
    }
    __syncthreads();

    for (int t = 0; t < NT; t++) {
        const int cur = t & 1, nxt = 1 - cur;
        const int k0n = (t + 1) * BKD;
        if (t + 1 < NT) {
#pragma unroll
            for (int p = 0; p < 4; p++)
                va[p] = aptr[p] ? *reinterpret_cast<const float4*>(aptr[p] + k0n)
                                : make_float4(0,0,0,0);
#pragma unroll
            for (int p = 0; p < 4; p++)
                vb[p] = *reinterpret_cast<const float4*>(
                    wd + (size_t)(k0n + brow + 8 * p) * H_DIM + h0 + bnq * 4);
        }

        const uint32_t* cA = sA + cur * DN_SA_STAGE;
        const uint32_t* cB = sB + cur * DN_SB_STAGE;
#pragma unroll
        for (int ks = 0; ks < 4; ks++) {
            uint32_t a[4][4], b[4][2];
#pragma unroll
            for (int mt = 0; mt < 4; mt++) {
                int rb = warp_m + mt * 16;
                a[mt][0] = cA[(rb + gid) * DN_SA_STRIDE + ks * 8 + t4];
                a[mt][1] = cA[(rb + gid + 8) * DN_SA_STRIDE + ks * 8 + t4];
                a[mt][2] = cA[(rb + gid) * DN_SA_STRIDE + ks * 8 + t4 + 4];
                a[mt][3] = cA[(rb + gid + 8) * DN_SA_STRIDE + ks * 8 + t4 + 4];
            }
#pragma unroll
            for (int nt = 0; nt < 4; nt++) {
                int c = warp_n + nt * 8 + gid;
                b[nt][0] = cB[(ks * 8 + t4) * DN_SB_STRIDE + c];
                b[nt][1] = cB[(ks * 8 + t4 + 4) * DN_SB_STRIDE + c];
            }
#pragma unroll
            for (int mt = 0; mt < 4; mt++)
#pragma unroll
                for (int nt = 0; nt < 4; nt++)
                    mma_tf32(acc[mt][nt], a[mt], b[nt]);
        }

        if (t + 1 < NT) {
#pragma unroll
            for (int p = 0; p < 4; p++) {
                *reinterpret_cast<float4*>(
                    &sA[nxt * DN_SA_STAGE + (arow + 32 * p) * DN_SA_STRIDE + akq * 4]) = va[p];
                uint4 ub = make_uint4(f2tf32(vb[p].x), f2tf32(vb[p].y), f2tf32(vb[p].z), f2tf32(vb[p].w));
                *reinterpret_cast<uint4*>(
                    &sB[nxt * DN_SB_STAGE + (brow + 8 * p) * DN_SB_STRIDE + bnq * 4]) = ub;
            }
        }
        __syncthreads();
    }

    // epilogue: scatter-add into y (exactly 2 expert contributions per token)
#pragma unroll
    for (int mt = 0; mt < 4; mt++) {
#pragma unroll
        for (int half = 0; half < 2; half++) {
            int m = m0 + warp_m + mt * 16 + gid + half * 8;
            if (m >= cnt) continue;
            int tok = g_tok[e * T_TOKENS + m];
            float* dst = y + (size_t)tok * H_DIM;
#pragma unroll
            for (int nt = 0; nt < 4; nt++) {
#pragma unroll
                for (int c = 0; c < 2; c++) {
                    int i = half * 2 + c;
                    int h = h0 + warp_n + nt * 8 + 2 * t4 + c;
                    atomicAdd(&dst[h], acc[mt][nt][i]);
                }
            }
        }
    }
}

// ---------------- launch ----------------
extern "C" void kernel_launch(void* const* d_in, const int* in_sizes, int n_in,
                              void* d_out, int out_size) {
    const float* x      = (const float*)d_in[0];  // [2,2048,1024]
    const float* gw     = (const float*)d_in[1];  // [1024,8]
    const float* w_up   = (const float*)d_in[2];  // [8,1024,3584]
    const float* w_gate = (const float*)d_in[3];  // [8,1024,3584]
    const float* w_down = (const float*)d_in[4];  // [8,3584,1024]

    float* out = (float*)d_out;
    float* y = out;                                    // [T, H]
    float* logits = out + (size_t)T_TOKENS * H_DIM;    // [T, E]

    static bool attr_done = false;
    if (!attr_done) {
        cudaFuncSetAttribute(upgate_kernel, cudaFuncAttributeMaxDynamicSharedMemorySize,
                             UG_SMEM_BYTES);
        cudaFuncSetAttribute(down_kernel, cudaFuncAttributeMaxDynamicSharedMemorySize,
                             DN_SMEM_BYTES);
        attr_done = true;
    }

    zero_kernel<<<512, 256>>>(y);
    router_kernel<<<T_TOKENS / 8, 256>>>(x, gw, logits);

    dim3 g2(F_DIM / BN, (T_TOKENS + BM - 1) / BM, NE);
    upgate_kernel<<<g2, 256, UG_SMEM_BYTES>>>(x, w_up, w_gate);

    dim3 g3(H_DIM / BN, (T_TOKENS + BM - 1) / BM, NE);
    down_kernel<<<g3, 256, DN_SMEM_BYTES>>>(w_down, y);
}